// round 13
// baseline (speedup 1.0000x reference)
#include <cuda_runtime.h>
#include <math.h>

#define E_N 250000
#define B_N 16
#define N_N 50000
#define R_N 500
#define DIN 100
#define D_  64
#define M_N 500000
#define TE  128    // edges per block in edge kernel
#define PR  128    // rows per tile in proj kernel
#define PK  50     // K per phase in proj kernel
#define PSTR2 51   // Xs row stride (odd, >=PK+1 -> 19*er+k mod 32 injective, conflict-free)

typedef unsigned long long ull;

// ---------------- f32x2 helpers ----------------
__device__ __forceinline__ ull dup2(float x) {
    ull r; asm("mov.b64 %0, {%1, %1};" : "=l"(r) : "f"(x)); return r;
}
__device__ __forceinline__ ull pk2(float x, float y) {
    ull r; asm("mov.b64 %0, {%1, %2};" : "=l"(r) : "f"(x), "f"(y)); return r;
}
__device__ __forceinline__ float2 unp2(ull v) {
    float2 f; asm("mov.b64 {%0, %1}, %2;" : "=f"(f.x), "=f"(f.y) : "l"(v)); return f;
}
__device__ __forceinline__ void fma2(ull& d, ull a, ull b) {
    asm("fma.rn.f32x2 %0, %1, %2, %0;" : "+l"(d) : "l"(a), "l"(b));
}
__device__ __forceinline__ ull add2(ull a, ull b) {
    ull r; asm("add.rn.f32x2 %0, %1, %2;" : "=l"(r) : "l"(a), "l"(b)); return r;
}
__device__ __forceinline__ ull leaky2(ull v) {
    float2 f = unp2(v);
    f.x = fmaxf(f.x, 0.2f * f.x);
    f.y = fmaxf(f.y, 0.2f * f.y);
    return pk2(f.x, f.y);
}
__device__ __forceinline__ float tanh_fast(float x) {
    float e = __expf(2.f * x);
    return __fdividef(e - 1.f, e + 1.f);
}

// ---------------- device scratch ----------------
__device__ float g_P[(size_t)M_N * D_];     // proj(hidden_con)
__device__ float g_PU[(size_t)N_N * D_];    // proj(hidden_uncon)
__device__ float g_relproj[R_N * D_];
__device__ float g_qproj[2 * B_N * D_];     // [qh ; qr]
__device__ float g_relc[4][R_N * D_];       // t: 0=g1l 1=g1r 2=g2l 3=g2r
__device__ float g_qc[4][B_N * D_];         // includes l/r bias
__device__ float g_logits[E_N];
__device__ float g_rowsum[B_N];
__device__ int   g_nused;

// ---------------- init ----------------
__global__ void init_kernel(float* out, int total) {
    int i = blockIdx.x * blockDim.x + threadIdx.x;
    if (i < total) out[i] = 0.f;
    if (i < B_N) g_rowsum[i] = 0.f;
    if (i == 0) g_nused = 0;
}

__global__ void nused_kernel(const int* __restrict__ edges) {
    __shared__ int s[256];
    int i = blockIdx.x * blockDim.x + threadIdx.x;
    int m = 0;
    for (int j = i; j < E_N; j += gridDim.x * blockDim.x)
        m = max(m, edges[j * 8 + 7]);
    s[threadIdx.x] = m;
    __syncthreads();
    for (int o = 128; o > 0; o >>= 1) {
        if (threadIdx.x < o) s[threadIdx.x] = max(s[threadIdx.x], s[threadIdx.x + o]);
        __syncthreads();
    }
    if (threadIdx.x == 0) atomicMax(&g_nused, s[0] + 1);
}

// ---------------- projection v10: proj6 with half-K double-phase A buffer.
// 256 threads, 128-row tile, 4x8 f32x2 fragments. Xs[128][51] (26.1KB) +
// Ws[100][64] (25.6KB) = 51.7KB -> 4 blocks/SM (32 warps). pb in registers.
__global__ void __launch_bounds__(256) proj10_kernel(
    const float* __restrict__ src,
    const float* __restrict__ pW, const float* __restrict__ pb,
    int rows, int dstSel)
{
    extern __shared__ __align__(16) float psm[];
    float* Xs = psm;                  // 128*51 = 6528 floats
    float* Ws = psm + PR * PSTR2;     // 100*64 = 6400 floats

    float* dst = (dstSel == 0) ? g_P
               : (dstSel == 1) ? g_PU
               : (dstSel == 2) ? g_relproj
               : (dstSel == 3) ? g_qproj
               : (g_qproj + B_N * D_);
    int rows_eff = (dstSel == 0) ? min(rows, g_nused) : rows;

    int row0 = blockIdx.x * PR;
    if (row0 >= rows_eff) return;

    int tid = threadIdx.x;
    const int er = tid & 31, cr = tid >> 5;

    // stage W coalesced (100x64 = 1600 float4)
    #pragma unroll
    for (int i = 0; i < 6; i++)
        ((float4*)Ws)[tid + i * 256] = ((const float4*)pW)[tid + i * 256];
    if (tid < 1600 - 6 * 256)
        ((float4*)Ws)[tid + 6 * 256] = ((const float4*)pW)[tid + 6 * 256];

    // pb: warp-uniform LDG into registers (cached, no smem)
    float4 pb0 = ((const float4*)pb)[cr * 2];
    float4 pb1 = ((const float4*)pb)[cr * 2 + 1];

    const float* xrow = Xs + er * PSTR2;
    bool full = (row0 + PR <= rows_eff);

    ull acc[4][4];
    #pragma unroll
    for (int i = 0; i < 4; i++)
        #pragma unroll
        for (int j = 0; j < 4; j++) acc[i][j] = 0ull;

    #pragma unroll
    for (int ph = 0; ph < 2; ph++) {
        int k0 = ph * PK;
        __syncthreads();   // Ws staged (ph 0) / prior-phase reads done (ph 1)

        // stage A[:, k0:k0+50]: 128 rows x 25 float2, SCALAR smem stores
        if (full) {
            #pragma unroll
            for (int it = 0; it < 12; it++) {
                int i = tid + it * 256;
                int r = i / 25, k2 = i - r * 25;
                float2 v = *(const float2*)(src + (size_t)(row0 + r) * DIN + k0 + k2 * 2);
                Xs[r * PSTR2 + k2 * 2]     = v.x;
                Xs[r * PSTR2 + k2 * 2 + 1] = v.y;
            }
            if (tid < 3200 - 12 * 256) {
                int i = tid + 12 * 256;
                int r = i / 25, k2 = i - r * 25;
                float2 v = *(const float2*)(src + (size_t)(row0 + r) * DIN + k0 + k2 * 2);
                Xs[r * PSTR2 + k2 * 2]     = v.x;
                Xs[r * PSTR2 + k2 * 2 + 1] = v.y;
            }
        } else {
            for (int i = tid; i < 3200; i += 256) {
                int r = i / 25, k2 = i - r * 25;
                int gr = row0 + r;
                float2 v = (gr < rows_eff)
                         ? *(const float2*)(src + (size_t)gr * DIN + k0 + k2 * 2)
                         : make_float2(0.f, 0.f);
                Xs[r * PSTR2 + k2 * 2]     = v.x;
                Xs[r * PSTR2 + k2 * 2 + 1] = v.y;
            }
        }
        __syncthreads();

        #pragma unroll 5
        for (int k = 0; k < PK; k++) {
            float a[4];
            #pragma unroll
            for (int i = 0; i < 4; i++) a[i] = xrow[i * (32 * PSTR2) + k];
            ulonglong2 b01 = *(const ulonglong2*)&Ws[(k0 + k) * 64 + cr * 8];
            ulonglong2 b23 = *(const ulonglong2*)&Ws[(k0 + k) * 64 + cr * 8 + 4];
            #pragma unroll
            for (int i = 0; i < 4; i++) {
                ull ad = dup2(a[i]);
                fma2(acc[i][0], ad, b01.x);
                fma2(acc[i][1], ad, b01.y);
                fma2(acc[i][2], ad, b23.x);
                fma2(acc[i][3], ad, b23.y);
            }
        }
    }

    // epilogue: bias + tanh, direct STG (two float4 per row)
    #pragma unroll
    for (int i = 0; i < 4; i++) {
        int gr = row0 + er + 32 * i;
        if (gr < rows_eff) {
            float2 f0 = unp2(acc[i][0]), f1 = unp2(acc[i][1]);
            float2 f2 = unp2(acc[i][2]), f3 = unp2(acc[i][3]);
            float4 o0, o1;
            o0.x = tanh_fast(f0.x + pb0.x);
            o0.y = tanh_fast(f0.y + pb0.y);
            o0.z = tanh_fast(f1.x + pb0.z);
            o0.w = tanh_fast(f1.y + pb0.w);
            o1.x = tanh_fast(f2.x + pb1.x);
            o1.y = tanh_fast(f2.y + pb1.y);
            o1.z = tanh_fast(f3.x + pb1.z);
            o1.w = tanh_fast(f3.y + pb1.w);
            float4* dp = (float4*)(dst + (size_t)gr * D_ + cr * 8);
            dp[0] = o0;
            dp[1] = o1;
        }
    }
}

// ---------------- rel / q contribution tables ----------------
__global__ void relc_kernel(const float* __restrict__ g1_lW, const float* __restrict__ g1_rW,
                            const float* __restrict__ g2_lW, const float* __restrict__ g2_rW)
{
    int b = blockIdx.x;
    int t = b / R_N, r = b % R_N;
    const float* W = (t == 0) ? g1_lW : (t == 1) ? g1_rW : (t == 2) ? g2_lW : g2_rW;
    __shared__ float x[64];
    int c = threadIdx.x;
    x[c] = g_relproj[r * 64 + c];
    __syncthreads();
    float s = 0.f;
    #pragma unroll
    for (int k = 0; k < 64; k++) s += x[k] * W[(64 + k) * 64 + c];
    g_relc[t][r * 64 + c] = s;
}

__global__ void qc_kernel(const float* __restrict__ g1_lW, const float* __restrict__ g1_rW,
                          const float* __restrict__ g2_lW, const float* __restrict__ g2_rW,
                          const float* __restrict__ g1_lb, const float* __restrict__ g1_rb,
                          const float* __restrict__ g2_lb, const float* __restrict__ g2_rb)
{
    int b = blockIdx.x;
    int t = b / B_N, q = b % B_N;
    const float* W  = (t == 0) ? g1_lW : (t == 1) ? g1_rW : (t == 2) ? g2_lW : g2_rW;
    const float* bi = (t == 0) ? g1_lb : (t == 1) ? g1_rb : (t == 2) ? g2_lb : g2_rb;
    __shared__ float xh[64], xr[64];
    int c = threadIdx.x;
    xh[c] = g_qproj[q * 64 + c];
    xr[c] = g_qproj[B_N * 64 + q * 64 + c];
    __syncthreads();
    float s = bi[c];
    #pragma unroll
    for (int k = 0; k < 64; k++) {
        s += xh[k] * W[(128 + k) * 64 + c];
        s += xr[k] * W[(192 + k) * 64 + c];
    }
    g_qc[t][q * 64 + c] = s;
}

// ---------------- edge kernel v4b (proven): 128-edge tile, 8x8 frags,
// f32x2, 32-slot smem hold
__global__ void __launch_bounds__(128) edge4_kernel(
    const int* __restrict__ edges,
    const float* __restrict__ g1_lW, const float* __restrict__ g1_rW,
    const float* __restrict__ g1_cW, const float* __restrict__ g1_cb,
    const float* __restrict__ g2_lW, const float* __restrict__ g2_rW,
    const float* __restrict__ g2_cW, const float* __restrict__ g2_cb)
{
    extern __shared__ __align__(16) char smraw[];
    float* Xs      = (float*)smraw;            // [64][128] = 32KB
    float* Ws      = Xs + 64 * TE;             // [64][64]  = 16KB
    ull*   Cs      = (ull*)(Ws + 64 * 64);     // 32 slots x 128 thr = 32KB
    int*   em_eg   = (int*)(Cs + 32 * 128);
    int*   em_rel  = em_eg + TE;
    int*   em_r2   = em_rel + TE;
    int*   em_r6   = em_r2 + TE;
    int*   em_r7   = em_r6 + TE;
    float* logit_s = (float*)(em_r7 + TE);     // [128]

    int tid = threadIdx.x;
    int b0 = blockIdx.x * TE;

    {
        int e = b0 + tid; if (e > E_N - 1) e = E_N - 1;
        int4 m0 = ((const int4*)edges)[(size_t)e * 2];
        int4 m1 = ((const int4*)edges)[(size_t)e * 2 + 1];
        em_eg[tid]  = m0.x;
        em_r2[tid]  = m0.z;   // vj (for h_uncon)
        em_rel[tid] = m0.w;   // rel
        em_r6[tid]  = m1.z;   // idx for h_vi
        em_r7[tid]  = m1.w;   // idx for h_vj
    }
    logit_s[tid] = 0.f;
    __syncthreads();

    const int er = tid & 15, cr = tid >> 4;

    int rel_r[8], eg_r[8];
    #pragma unroll
    for (int i = 0; i < 8; i++) { rel_r[i] = em_rel[er * 8 + i]; eg_r[i] = em_eg[er * 8 + i]; }

    ull acc[8][4], dot2[8];
    #pragma unroll
    for (int i = 0; i < 8; i++) dot2[i] = 0ull;

    auto loadW = [&](const float* __restrict__ W) {
        const float4* s = (const float4*)W;
        float4* d = (float4*)Ws;
        #pragma unroll
        for (int i = 0; i < 8; i++) d[tid + i * 128] = s[tid + i * 128];
    };
    auto gatherP = [&](const float* __restrict__ tab, const int* ridx) {
        int r = ridx[tid];
        const float4* s = (const float4*)(tab + (size_t)r * 64);
        #pragma unroll
        for (int q = 0; q < 16; q++) {
            float4 v = s[q];
            Xs[(q * 4 + 0) * TE + tid] = v.x;
            Xs[(q * 4 + 1) * TE + tid] = v.y;
            Xs[(q * 4 + 2) * TE + tid] = v.z;
            Xs[(q * 4 + 3) * TE + tid] = v.w;
        }
    };
    auto gemm = [&]() {
        #pragma unroll
        for (int i = 0; i < 8; i++)
            #pragma unroll
            for (int jp = 0; jp < 4; jp++) acc[i][jp] = 0ull;
        #pragma unroll 4
        for (int k = 0; k < 64; k++) {
            float a[8];
            *(float4*)&a[0] = *(const float4*)&Xs[k * TE + er * 8];
            *(float4*)&a[4] = *(const float4*)&Xs[k * TE + er * 8 + 4];
            ulonglong2 b01 = *(const ulonglong2*)&Ws[k * 64 + cr * 8];
            ulonglong2 b23 = *(const ulonglong2*)&Ws[k * 64 + cr * 8 + 4];
            #pragma unroll
            for (int i = 0; i < 8; i++) {
                ull ad = dup2(a[i]);
                fma2(acc[i][0], ad, b01.x);
                fma2(acc[i][1], ad, b01.y);
                fma2(acc[i][2], ad, b23.x);
                fma2(acc[i][3], ad, b23.y);
            }
        }
    };
    auto epi = [&](const float* __restrict__ relcT, const float* __restrict__ qcT) {
        #pragma unroll
        for (int i = 0; i < 8; i++) {
            const float4* rp = (const float4*)(relcT + rel_r[i] * 64 + cr * 8);
            const float4* qp = (const float4*)(qcT + eg_r[i] * 64 + cr * 8);
            float4 r0 = rp[0], r1 = rp[1], q0 = qp[0], q1 = qp[1];
            acc[i][0] = leaky2(add2(acc[i][0], pk2(r0.x + q0.x, r0.y + q0.y)));
            acc[i][1] = leaky2(add2(acc[i][1], pk2(r0.z + q0.z, r0.w + q0.w)));
            acc[i][2] = leaky2(add2(acc[i][2], pk2(r1.x + q1.x, r1.y + q1.y)));
            acc[i][3] = leaky2(add2(acc[i][3], pk2(r1.z + q1.z, r1.w + q1.w)));
        }
    };
    auto writeR = [&]() {
        float Rf[8][8];
        #pragma unroll
        for (int i = 0; i < 8; i++) {
            float2 f0 = unp2(acc[i][0]), f1 = unp2(acc[i][1]);
            float2 f2 = unp2(acc[i][2]), f3 = unp2(acc[i][3]);
            Rf[i][0] = f0.x; Rf[i][1] = f0.y; Rf[i][2] = f1.x; Rf[i][3] = f1.y;
            Rf[i][4] = f2.x; Rf[i][5] = f2.y; Rf[i][6] = f3.x; Rf[i][7] = f3.y;
        }
        #pragma unroll
        for (int j = 0; j < 8; j++) {
            int c = cr * 8 + j;
            float4 v0 = make_float4(Rf[0][j], Rf[1][j], Rf[2][j], Rf[3][j]);
            float4 v1 = make_float4(Rf[4][j], Rf[5][j], Rf[6][j], Rf[7][j]);
            *(float4*)&Xs[c * TE + er * 8]     = v0;
            *(float4*)&Xs[c * TE + er * 8 + 4] = v1;
        }
    };
    auto loadCbp = [&](const float* __restrict__ cb, ull cbp[4]) {
        float4 c0 = *(const float4*)(cb + cr * 8);
        float4 c1 = *(const float4*)(cb + cr * 8 + 4);
        cbp[0] = pk2(c0.x, c0.y); cbp[1] = pk2(c0.z, c0.w);
        cbp[2] = pk2(c1.x, c1.y); cbp[3] = pk2(c1.z, c1.w);
    };

    // step 1: R1 = leaky(P[r7] @ g1_rW_x + relc1 + qc1)
    gatherP(g_P, em_r7); loadW(g1_rW);
    __syncthreads();
    gemm(); epi(g_relc[1], g_qc[1]);
    __syncthreads();
    // step 2: C1 = R1 @ g1_cW + cb1 -> Cs (thread-private smem hold)
    writeR(); loadW(g1_cW);
    __syncthreads();
    gemm();
    {
        ull cbp[4]; loadCbp(g1_cb, cbp);
        #pragma unroll
        for (int i = 0; i < 8; i++)
            #pragma unroll
            for (int jp = 0; jp < 4; jp++)
                Cs[(i * 4 + jp) * 128 + tid] = add2(acc[i][jp], cbp[jp]);
    }
    __syncthreads();
    // step 3: L1 = leaky(P[r6] @ g1_lW_x + ...); dot2 += L1 . Cs
    gatherP(g_P, em_r6); loadW(g1_lW);
    __syncthreads();
    gemm(); epi(g_relc[0], g_qc[0]);
    #pragma unroll
    for (int i = 0; i < 8; i++)
        #pragma unroll
        for (int jp = 0; jp < 4; jp++)
            fma2(dot2[i], acc[i][jp], Cs[(i * 4 + jp) * 128 + tid]);
    __syncthreads();
    // step 4: L2 (same X) -> Cs
    loadW(g2_lW);
    __syncthreads();
    gemm(); epi(g_relc[2], g_qc[2]);
    #pragma unroll
    for (int i = 0; i < 8; i++)
        #pragma unroll
        for (int jp = 0; jp < 4; jp++)
            Cs[(i * 4 + jp) * 128 + tid] = acc[i][jp];
    __syncthreads();
    // step 5: R2 = leaky(PU[vj] @ g2_rW_x + ...)
    gatherP(g_PU, em_r2); loadW(g2_rW);
    __syncthreads();
    gemm(); epi(g_relc[3], g_qc[3]);
    __syncthreads();
    // step 6: C2 = R2 @ g2_cW + cb2; dot2 += Cs(L2) . (C2+cb2)
    writeR(); loadW(g2_cW);
    __syncthreads();
    gemm();
    {
        ull cbp[4]; loadCbp(g2_cb, cbp);
        #pragma unroll
        for (int i = 0; i < 8; i++)
            #pragma unroll
            for (int jp = 0; jp < 4; jp++)
                fma2(dot2[i], Cs[(i * 4 + jp) * 128 + tid], add2(acc[i][jp], cbp[jp]));
    }

    // reduce over cr, write logits
    #pragma unroll
    for (int i = 0; i < 8; i++) {
        float2 f = unp2(dot2[i]);
        float p = f.x + f.y;
        p += __shfl_xor_sync(0xffffffffu, p, 16);
        if ((cr & 1) == 0) atomicAdd(&logit_s[er * 8 + i], p);
    }
    __syncthreads();
    if (b0 + tid < E_N) g_logits[b0 + tid] = logit_s[tid];
}

// ---------------- segmented softmax + scatter (v2: length-1 fast path) ----------------
__global__ void seg_kernel(const int* __restrict__ edges, const float* __restrict__ na,
                           float* __restrict__ out)
{
    __shared__ float rs[B_N];
    if (threadIdx.x < B_N) rs[threadIdx.x] = 0.f;
    __syncthreads();

    int i = blockIdx.x * blockDim.x + threadIdx.x;
    if (i < E_N) {
        int ivi = __ldg(&edges[i * 8 + 4]);
        bool head = (i == 0) || (__ldg(&edges[(i - 1) * 8 + 4]) != ivi);
        if (head) {
            int j = i + 1;
            while (j < E_N && __ldg(&edges[j * 8 + 4]) == ivi) j++;
            int eg = edges[i * 8 + 0], vi = edges[i * 8 + 1];
            float base = __ldg(&na[eg * N_N + vi]);
            if (j == i + 1) {
                atomicAdd(&out[eg * N_N + edges[i * 8 + 2]], base);
                atomicAdd(&rs[eg], base);
            } else {
                float m = -1e30f;
                for (int q = i; q < j; q++) m = fmaxf(m, g_logits[q]);
                float den = 0.f;
                for (int q = i; q < j; q++) den += __expf(g_logits[q] - m);
                float inv = base / den;
                float segsum = 0.f;
                for (int q = i; q < j; q++) {
                    int vj = edges[q * 8 + 2];
                    float t = __expf(g_logits[q] - m) * inv;
                    atomicAdd(&out[eg * N_N + vj], t);
                    segsum += t;
                }
                atomicAdd(&rs[eg], segsum);
            }
        }
    }
    __syncthreads();
    if (threadIdx.x < B_N) {
        float v = rs[threadIdx.x];
        if (v != 0.f) atomicAdd(&g_rowsum[threadIdx.x], v);
    }
}

__global__ void norm_kernel(float* out) {
    int i = blockIdx.x * blockDim.x + threadIdx.x;
    if (i < B_N * N_N) out[i] = out[i] / g_rowsum[i / N_N];
}

// ---------------- launch ----------------
extern "C" void kernel_launch(void* const* d_in, const int* in_sizes, int n_in,
                              void* d_out, int out_size)
{
    const float* na        = (const float*)d_in[0];
    const int*   edges     = (const int*)d_in[1];
    const float* h_uncon   = (const float*)d_in[2];
    const float* h_con     = (const float*)d_in[3];
    const float* rel_table = (const float*)d_in[4];
    const float* qh        = (const float*)d_in[5];
    const float* qr        = (const float*)d_in[6];
    const float* pW        = (const float*)d_in[7];
    const float* pb        = (const float*)d_in[8];
    const float* g1_lW     = (const float*)d_in[9];
    const float* g1_lb     = (const float*)d_in[10];
    const float* g1_rW     = (const float*)d_in[11];
    const float* g1_rb     = (const float*)d_in[12];
    const float* g1_cW     = (const float*)d_in[13];
    const float* g1_cb     = (const float*)d_in[14];
    const float* g2_lW     = (const float*)d_in[15];
    const float* g2_lb     = (const float*)d_in[16];
    const float* g2_rW     = (const float*)d_in[17];
    const float* g2_rb     = (const float*)d_in[18];
    const float* g2_cW     = (const float*)d_in[19];
    const float* g2_cb     = (const float*)d_in[20];
    float* out = (float*)d_out;

    const int PROJ_SMEM = (PR * PSTR2 + DIN * D_) * 4;                     // 51712
    const int EDGE_SMEM = (64 * TE + 64 * 64) * 4 + 32 * 128 * 8 + 5 * TE * 4 + TE * 4;  // 84992
    cudaFuncSetAttribute(proj10_kernel, cudaFuncAttributeMaxDynamicSharedMemorySize, PROJ_SMEM);
    cudaFuncSetAttribute(edge4_kernel, cudaFuncAttributeMaxDynamicSharedMemorySize, EDGE_SMEM);

    init_kernel<<<(B_N * N_N + 255) / 256, 256>>>(out, B_N * N_N);
    nused_kernel<<<256, 256>>>(edges);

    proj10_kernel<<<(M_N + PR - 1) / PR, 256, PROJ_SMEM>>>(h_con,     pW, pb, M_N, 0);
    proj10_kernel<<<(N_N + PR - 1) / PR, 256, PROJ_SMEM>>>(h_uncon,   pW, pb, N_N, 1);
    proj10_kernel<<<(R_N + PR - 1) / PR, 256, PROJ_SMEM>>>(rel_table, pW, pb, R_N, 2);
    proj10_kernel<<<1, 256, PROJ_SMEM>>>(qh, pW, pb, B_N, 3);
    proj10_kernel<<<1, 256, PROJ_SMEM>>>(qr, pW, pb, B_N, 4);

    relc_kernel<<<4 * R_N, 64>>>(g1_lW, g1_rW, g2_lW, g2_rW);
    qc_kernel<<<4 * B_N, 64>>>(g1_lW, g1_rW, g2_lW, g2_rW, g1_lb, g1_rb, g2_lb, g2_rb);

    edge4_kernel<<<(E_N + TE - 1) / TE, TE, EDGE_SMEM>>>(edges,
        g1_lW, g1_rW, g1_cW, g1_cb, g2_lW, g2_rW, g2_cW, g2_cb);

    seg_kernel<<<(E_N + 255) / 256, 256>>>(edges, na, out);
    norm_kernel<<<(B_N * N_N + 255) / 256, 256>>>(out);
}

// round 14
// speedup vs baseline: 1.0749x; 1.0749x over previous
#include <cuda_runtime.h>
#include <math.h>

#define E_N 250000
#define B_N 16
#define N_N 50000
#define R_N 500
#define DIN 100
#define D_  64
#define M_N 500000
#define TE  128   // edges per block in edge kernel
#define PR  128   // rows per tile in proj kernel
#define PSTR 103  // Xs row stride (odd -> conflict-free scalar A reads)

typedef unsigned long long ull;

// ---------------- f32x2 helpers ----------------
__device__ __forceinline__ ull dup2(float x) {
    ull r; asm("mov.b64 %0, {%1, %1};" : "=l"(r) : "f"(x)); return r;
}
__device__ __forceinline__ ull pk2(float x, float y) {
    ull r; asm("mov.b64 %0, {%1, %2};" : "=l"(r) : "f"(x), "f"(y)); return r;
}
__device__ __forceinline__ float2 unp2(ull v) {
    float2 f; asm("mov.b64 {%0, %1}, %2;" : "=f"(f.x), "=f"(f.y) : "l"(v)); return f;
}
__device__ __forceinline__ void fma2(ull& d, ull a, ull b) {
    asm("fma.rn.f32x2 %0, %1, %2, %0;" : "+l"(d) : "l"(a), "l"(b));
}
__device__ __forceinline__ ull add2(ull a, ull b) {
    ull r; asm("add.rn.f32x2 %0, %1, %2;" : "=l"(r) : "l"(a), "l"(b)); return r;
}
__device__ __forceinline__ ull leaky2(ull v) {
    float2 f = unp2(v);
    f.x = fmaxf(f.x, 0.2f * f.x);
    f.y = fmaxf(f.y, 0.2f * f.y);
    return pk2(f.x, f.y);
}
__device__ __forceinline__ float tanh_fast(float x) {
    float e = __expf(2.f * x);
    return __fdividef(e - 1.f, e + 1.f);
}

// ---------------- device scratch ----------------
__device__ float g_P[(size_t)M_N * D_];     // proj(hidden_con)
__device__ float g_PU[(size_t)N_N * D_];    // proj(hidden_uncon)
__device__ float g_relproj[R_N * D_];
__device__ float g_qproj[2 * B_N * D_];     // [qh ; qr]
__device__ float g_relc[4][R_N * D_];       // t: 0=g1l 1=g1r 2=g2l 3=g2r
__device__ float g_qc[4][B_N * D_];         // includes l/r bias
__device__ float g_logits[E_N];
__device__ float g_rowsum[B_N];
__device__ int   g_nused;

// ---------------- fused init + nused ----------------
__global__ void init_nused_kernel(float* out, int total, const int* __restrict__ edges) {
    int i = blockIdx.x * blockDim.x + threadIdx.x;
    if (i < total) out[i] = 0.f;
    if (i < B_N) g_rowsum[i] = 0.f;
    if (i == 0) g_nused = 0;
    // nused reduction over a subset of blocks (grid is ~3125 blocks; use all)
    __shared__ int s[256];
    int m = 0;
    int stride = gridDim.x * blockDim.x;
    for (int j = i; j < E_N; j += stride)
        m = max(m, __ldg(&edges[j * 8 + 7]));
    s[threadIdx.x] = m;
    __syncthreads();
    for (int o = 128; o > 0; o >>= 1) {
        if (threadIdx.x < o) s[threadIdx.x] = max(s[threadIdx.x], s[threadIdx.x + o]);
        __syncthreads();
    }
    if (threadIdx.x == 0) atomicMax(&g_nused, s[0] + 1);
}

// ---------------- projection v6 (R12-proven): 256 threads, 128-row tile,
// 4x8 f32x2 fragments. dstSel==5 -> fused small inputs (rel/qh/qr) by blockIdx.
__global__ void __launch_bounds__(256) proj6_kernel(
    const float* __restrict__ src,
    const float* __restrict__ pW, const float* __restrict__ pb,
    int rows, int dstSel,
    const float* __restrict__ src_b, const float* __restrict__ src_c)
{
    extern __shared__ __align__(16) float psm[];
    float* Xs  = psm;                  // 128*103 = 13184
    float* Ws  = psm + PR * PSTR;      // 100*64  = 6400
    float* pbs = Ws + DIN * D_;        // 64

    float* dst;
    int rows_eff;
    int row0;
    if (dstSel == 5) {
        // fused small inputs: blocks 0..3 -> rel_table rows, block 4 -> qh(16)+qr(16)
        if (blockIdx.x < 4) {
            dst = g_relproj; rows_eff = R_N; row0 = blockIdx.x * PR;
            if (row0 >= rows_eff) return;
        } else {
            dst = g_qproj; rows_eff = 2 * B_N; row0 = 0;
        }
    } else {
        dst = (dstSel == 0) ? g_P : g_PU;
        rows_eff = (dstSel == 0) ? min(rows, g_nused) : rows;
        row0 = blockIdx.x * PR;
        if (row0 >= rows_eff) return;
    }

    int tid = threadIdx.x;

    // stage W coalesced (100x64 = 1600 float4)
    #pragma unroll
    for (int i = 0; i < 6; i++)
        ((float4*)Ws)[tid + i * 256] = ((const float4*)pW)[tid + i * 256];
    if (tid < 1600 - 6 * 256)
        ((float4*)Ws)[tid + 6 * 256] = ((const float4*)pW)[tid + 6 * 256];
    if (tid < 64) pbs[tid] = pb[tid];

    // stage A: 128 rows x 50 float2 gmem reads, SCALAR smem stores (odd stride)
    bool full = (dstSel != 5) && (row0 + PR <= rows_eff);
    if (full) {
        const float2* s2 = (const float2*)(src + (size_t)row0 * DIN);
        #pragma unroll
        for (int it = 0; it < 25; it++) {
            int i = tid + it * 256;
            int r = i / 50, k2 = i - r * 50;
            float2 v = s2[i];
            Xs[r * PSTR + k2 * 2]     = v.x;
            Xs[r * PSTR + k2 * 2 + 1] = v.y;
        }
    } else if (dstSel == 5 && blockIdx.x == 4) {
        // rows 0..15 from src_b (qh), rows 16..31 from src_c (qr); rest zero
        for (int i = tid; i < 6400; i += 256) {
            int r = i / 50, k2 = i - r * 50;
            float2 v = make_float2(0.f, 0.f);
            if (r < B_N) v = ((const float2*)(src_b + (size_t)r * DIN))[k2];
            else if (r < 2 * B_N) v = ((const float2*)(src_c + (size_t)(r - B_N) * DIN))[k2];
            Xs[r * PSTR + k2 * 2]     = v.x;
            Xs[r * PSTR + k2 * 2 + 1] = v.y;
        }
    } else {
        for (int i = tid; i < 6400; i += 256) {
            int r = i / 50, k2 = i - r * 50;
            int gr = row0 + r;
            float2 v = (gr < rows_eff)
                     ? ((const float2*)(src + (size_t)gr * DIN))[k2]
                     : make_float2(0.f, 0.f);
            Xs[r * PSTR + k2 * 2]     = v.x;
            Xs[r * PSTR + k2 * 2 + 1] = v.y;
        }
    }
    __syncthreads();

    const int er = tid & 31, cr = tid >> 5;
    const float* xrow = Xs + er * PSTR;

    ull acc[4][4];
    #pragma unroll
    for (int i = 0; i < 4; i++)
        #pragma unroll
        for (int j = 0; j < 4; j++) acc[i][j] = 0ull;

    #pragma unroll 4
    for (int k = 0; k < DIN; k++) {
        float a[4];
        #pragma unroll
        for (int i = 0; i < 4; i++) a[i] = xrow[i * (32 * PSTR) + k];
        ulonglong2 b01 = *(const ulonglong2*)&Ws[k * 64 + cr * 8];
        ulonglong2 b23 = *(const ulonglong2*)&Ws[k * 64 + cr * 8 + 4];
        #pragma unroll
        for (int i = 0; i < 4; i++) {
            ull ad = dup2(a[i]);
            fma2(acc[i][0], ad, b01.x);
            fma2(acc[i][1], ad, b01.y);
            fma2(acc[i][2], ad, b23.x);
            fma2(acc[i][3], ad, b23.y);
        }
    }

    // epilogue: bias + tanh, direct STG (two float4 per row)
    float4 pb0 = *(const float4*)&pbs[cr * 8];
    float4 pb1 = *(const float4*)&pbs[cr * 8 + 4];
    #pragma unroll
    for (int i = 0; i < 4; i++) {
        int gr = row0 + er + 32 * i;
        if (gr < rows_eff) {
            float2 f0 = unp2(acc[i][0]), f1 = unp2(acc[i][1]);
            float2 f2 = unp2(acc[i][2]), f3 = unp2(acc[i][3]);
            float4 o0, o1;
            o0.x = tanh_fast(f0.x + pb0.x);
            o0.y = tanh_fast(f0.y + pb0.y);
            o0.z = tanh_fast(f1.x + pb0.z);
            o0.w = tanh_fast(f1.y + pb0.w);
            o1.x = tanh_fast(f2.x + pb1.x);
            o1.y = tanh_fast(f2.y + pb1.y);
            o1.z = tanh_fast(f3.x + pb1.z);
            o1.w = tanh_fast(f3.y + pb1.w);
            float4* dp = (float4*)(dst + (size_t)gr * D_ + cr * 8);
            dp[0] = o0;
            dp[1] = o1;
        }
    }
}

// ---------------- fused rel + q contribution tables ----------------
// blocks 0..1999: relc (t = b/500, r = b%500); blocks 2000..2063: qc (t = .., q = ..)
__global__ void tables_kernel(
    const float* __restrict__ g1_lW, const float* __restrict__ g1_rW,
    const float* __restrict__ g2_lW, const float* __restrict__ g2_rW,
    const float* __restrict__ g1_lb, const float* __restrict__ g1_rb,
    const float* __restrict__ g2_lb, const float* __restrict__ g2_rb)
{
    int b = blockIdx.x;
    int c = threadIdx.x;
    if (b < 4 * R_N) {
        int t = b / R_N, r = b % R_N;
        const float* W = (t == 0) ? g1_lW : (t == 1) ? g1_rW : (t == 2) ? g2_lW : g2_rW;
        __shared__ float x[64];
        x[c] = g_relproj[r * 64 + c];
        __syncthreads();
        float s = 0.f;
        #pragma unroll
        for (int k = 0; k < 64; k++) s += x[k] * W[(64 + k) * 64 + c];
        g_relc[t][r * 64 + c] = s;
    } else {
        int bb = b - 4 * R_N;
        int t = bb / B_N, q = bb % B_N;
        const float* W  = (t == 0) ? g1_lW : (t == 1) ? g1_rW : (t == 2) ? g2_lW : g2_rW;
        const float* bi = (t == 0) ? g1_lb : (t == 1) ? g1_rb : (t == 2) ? g2_lb : g2_rb;
        __shared__ float xh[64], xr[64];
        xh[c] = g_qproj[q * 64 + c];
        xr[c] = g_qproj[B_N * 64 + q * 64 + c];
        __syncthreads();
        float s = bi[c];
        #pragma unroll
        for (int k = 0; k < 64; k++) {
            s += xh[k] * W[(128 + k) * 64 + c];
            s += xr[k] * W[(192 + k) * 64 + c];
        }
        g_qc[t][q * 64 + c] = s;
    }
}

// ---------------- edge kernel v4b (proven): 128-edge tile, 8x8 frags,
// f32x2, 32-slot smem hold
__global__ void __launch_bounds__(128) edge4_kernel(
    const int* __restrict__ edges,
    const float* __restrict__ g1_lW, const float* __restrict__ g1_rW,
    const float* __restrict__ g1_cW, const float* __restrict__ g1_cb,
    const float* __restrict__ g2_lW, const float* __restrict__ g2_rW,
    const float* __restrict__ g2_cW, const float* __restrict__ g2_cb)
{
    extern __shared__ __align__(16) char smraw[];
    float* Xs      = (float*)smraw;            // [64][128] = 32KB
    float* Ws      = Xs + 64 * TE;             // [64][64]  = 16KB
    ull*   Cs      = (ull*)(Ws + 64 * 64);     // 32 slots x 128 thr = 32KB
    int*   em_eg   = (int*)(Cs + 32 * 128);
    int*   em_rel  = em_eg + TE;
    int*   em_r2   = em_rel + TE;
    int*   em_r6   = em_r2 + TE;
    int*   em_r7   = em_r6 + TE;
    float* logit_s = (float*)(em_r7 + TE);     // [128]

    int tid = threadIdx.x;
    int b0 = blockIdx.x * TE;

    {
        int e = b0 + tid; if (e > E_N - 1) e = E_N - 1;
        int4 m0 = ((const int4*)edges)[(size_t)e * 2];
        int4 m1 = ((const int4*)edges)[(size_t)e * 2 + 1];
        em_eg[tid]  = m0.x;
        em_r2[tid]  = m0.z;   // vj (for h_uncon)
        em_rel[tid] = m0.w;   // rel
        em_r6[tid]  = m1.z;   // idx for h_vi
        em_r7[tid]  = m1.w;   // idx for h_vj
    }
    logit_s[tid] = 0.f;
    __syncthreads();

    const int er = tid & 15, cr = tid >> 4;

    int rel_r[8], eg_r[8];
    #pragma unroll
    for (int i = 0; i < 8; i++) { rel_r[i] = em_rel[er * 8 + i]; eg_r[i] = em_eg[er * 8 + i]; }

    ull acc[8][4], dot2[8];
    #pragma unroll
    for (int i = 0; i < 8; i++) dot2[i] = 0ull;

    auto loadW = [&](const float* __restrict__ W) {
        const float4* s = (const float4*)W;
        float4* d = (float4*)Ws;
        #pragma unroll
        for (int i = 0; i < 8; i++) d[tid + i * 128] = s[tid + i * 128];
    };
    auto gatherP = [&](const float* __restrict__ tab, const int* ridx) {
        int r = ridx[tid];
        const float4* s = (const float4*)(tab + (size_t)r * 64);
        #pragma unroll
        for (int q = 0; q < 16; q++) {
            float4 v = s[q];
            Xs[(q * 4 + 0) * TE + tid] = v.x;
            Xs[(q * 4 + 1) * TE + tid] = v.y;
            Xs[(q * 4 + 2) * TE + tid] = v.z;
            Xs[(q * 4 + 3) * TE + tid] = v.w;
        }
    };
    auto gemm = [&]() {
        #pragma unroll
        for (int i = 0; i < 8; i++)
            #pragma unroll
            for (int jp = 0; jp < 4; jp++) acc[i][jp] = 0ull;
        #pragma unroll 4
        for (int k = 0; k < 64; k++) {
            float a[8];
            *(float4*)&a[0] = *(const float4*)&Xs[k * TE + er * 8];
            *(float4*)&a[4] = *(const float4*)&Xs[k * TE + er * 8 + 4];
            ulonglong2 b01 = *(const ulonglong2*)&Ws[k * 64 + cr * 8];
            ulonglong2 b23 = *(const ulonglong2*)&Ws[k * 64 + cr * 8 + 4];
            #pragma unroll
            for (int i = 0; i < 8; i++) {
                ull ad = dup2(a[i]);
                fma2(acc[i][0], ad, b01.x);
                fma2(acc[i][1], ad, b01.y);
                fma2(acc[i][2], ad, b23.x);
                fma2(acc[i][3], ad, b23.y);
            }
        }
    };
    auto epi = [&](const float* __restrict__ relcT, const float* __restrict__ qcT) {
        #pragma unroll
        for (int i = 0; i < 8; i++) {
            const float4* rp = (const float4*)(relcT + rel_r[i] * 64 + cr * 8);
            const float4* qp = (const float4*)(qcT + eg_r[i] * 64 + cr * 8);
            float4 r0 = rp[0], r1 = rp[1], q0 = qp[0], q1 = qp[1];
            acc[i][0] = leaky2(add2(acc[i][0], pk2(r0.x + q0.x, r0.y + q0.y)));
            acc[i][1] = leaky2(add2(acc[i][1], pk2(r0.z + q0.z, r0.w + q0.w)));
            acc[i][2] = leaky2(add2(acc[i][2], pk2(r1.x + q1.x, r1.y + q1.y)));
            acc[i][3] = leaky2(add2(acc[i][3], pk2(r1.z + q1.z, r1.w + q1.w)));
        }
    };
    auto writeR = [&]() {
        float Rf[8][8];
        #pragma unroll
        for (int i = 0; i < 8; i++) {
            float2 f0 = unp2(acc[i][0]), f1 = unp2(acc[i][1]);
            float2 f2 = unp2(acc[i][2]), f3 = unp2(acc[i][3]);
            Rf[i][0] = f0.x; Rf[i][1] = f0.y; Rf[i][2] = f1.x; Rf[i][3] = f1.y;
            Rf[i][4] = f2.x; Rf[i][5] = f2.y; Rf[i][6] = f3.x; Rf[i][7] = f3.y;
        }
        #pragma unroll
        for (int j = 0; j < 8; j++) {
            int c = cr * 8 + j;
            float4 v0 = make_float4(Rf[0][j], Rf[1][j], Rf[2][j], Rf[3][j]);
            float4 v1 = make_float4(Rf[4][j], Rf[5][j], Rf[6][j], Rf[7][j]);
            *(float4*)&Xs[c * TE + er * 8]     = v0;
            *(float4*)&Xs[c * TE + er * 8 + 4] = v1;
        }
    };
    auto loadCbp = [&](const float* __restrict__ cb, ull cbp[4]) {
        float4 c0 = *(const float4*)(cb + cr * 8);
        float4 c1 = *(const float4*)(cb + cr * 8 + 4);
        cbp[0] = pk2(c0.x, c0.y); cbp[1] = pk2(c0.z, c0.w);
        cbp[2] = pk2(c1.x, c1.y); cbp[3] = pk2(c1.z, c1.w);
    };

    // step 1: R1 = leaky(P[r7] @ g1_rW_x + relc1 + qc1)
    gatherP(g_P, em_r7); loadW(g1_rW);
    __syncthreads();
    gemm(); epi(g_relc[1], g_qc[1]);
    __syncthreads();
    // step 2: C1 = R1 @ g1_cW + cb1 -> Cs (thread-private smem hold)
    writeR(); loadW(g1_cW);
    __syncthreads();
    gemm();
    {
        ull cbp[4]; loadCbp(g1_cb, cbp);
        #pragma unroll
        for (int i = 0; i < 8; i++)
            #pragma unroll
            for (int jp = 0; jp < 4; jp++)
                Cs[(i * 4 + jp) * 128 + tid] = add2(acc[i][jp], cbp[jp]);
    }
    __syncthreads();
    // step 3: L1 = leaky(P[r6] @ g1_lW_x + ...); dot2 += L1 . Cs
    gatherP(g_P, em_r6); loadW(g1_lW);
    __syncthreads();
    gemm(); epi(g_relc[0], g_qc[0]);
    #pragma unroll
    for (int i = 0; i < 8; i++)
        #pragma unroll
        for (int jp = 0; jp < 4; jp++)
            fma2(dot2[i], acc[i][jp], Cs[(i * 4 + jp) * 128 + tid]);
    __syncthreads();
    // step 4: L2 (same X) -> Cs
    loadW(g2_lW);
    __syncthreads();
    gemm(); epi(g_relc[2], g_qc[2]);
    #pragma unroll
    for (int i = 0; i < 8; i++)
        #pragma unroll
        for (int jp = 0; jp < 4; jp++)
            Cs[(i * 4 + jp) * 128 + tid] = acc[i][jp];
    __syncthreads();
    // step 5: R2 = leaky(PU[vj] @ g2_rW_x + ...)
    gatherP(g_PU, em_r2); loadW(g2_rW);
    __syncthreads();
    gemm(); epi(g_relc[3], g_qc[3]);
    __syncthreads();
    // step 6: C2 = R2 @ g2_cW + cb2; dot2 += Cs(L2) . (C2+cb2)
    writeR(); loadW(g2_cW);
    __syncthreads();
    gemm();
    {
        ull cbp[4]; loadCbp(g2_cb, cbp);
        #pragma unroll
        for (int i = 0; i < 8; i++)
            #pragma unroll
            for (int jp = 0; jp < 4; jp++)
                fma2(dot2[i], Cs[(i * 4 + jp) * 128 + tid], add2(acc[i][jp], cbp[jp]));
    }

    // reduce over cr, write logits
    #pragma unroll
    for (int i = 0; i < 8; i++) {
        float2 f = unp2(dot2[i]);
        float p = f.x + f.y;
        p += __shfl_xor_sync(0xffffffffu, p, 16);
        if ((cr & 1) == 0) atomicAdd(&logit_s[er * 8 + i], p);
    }
    __syncthreads();
    if (b0 + tid < E_N) g_logits[b0 + tid] = logit_s[tid];
}

// ---------------- segmented softmax + scatter (v2: length-1 fast path) ----------------
__global__ void seg_kernel(const int* __restrict__ edges, const float* __restrict__ na,
                           float* __restrict__ out)
{
    __shared__ float rs[B_N];
    if (threadIdx.x < B_N) rs[threadIdx.x] = 0.f;
    __syncthreads();

    int i = blockIdx.x * blockDim.x + threadIdx.x;
    if (i < E_N) {
        int ivi = __ldg(&edges[i * 8 + 4]);
        bool head = (i == 0) || (__ldg(&edges[(i - 1) * 8 + 4]) != ivi);
        if (head) {
            int j = i + 1;
            while (j < E_N && __ldg(&edges[j * 8 + 4]) == ivi) j++;
            int eg = edges[i * 8 + 0], vi = edges[i * 8 + 1];
            float base = __ldg(&na[eg * N_N + vi]);
            if (j == i + 1) {
                atomicAdd(&out[eg * N_N + edges[i * 8 + 2]], base);
                atomicAdd(&rs[eg], base);
            } else {
                float m = -1e30f;
                for (int q = i; q < j; q++) m = fmaxf(m, g_logits[q]);
                float den = 0.f;
                for (int q = i; q < j; q++) den += __expf(g_logits[q] - m);
                float inv = base / den;
                float segsum = 0.f;
                for (int q = i; q < j; q++) {
                    int vj = edges[q * 8 + 2];
                    float t = __expf(g_logits[q] - m) * inv;
                    atomicAdd(&out[eg * N_N + vj], t);
                    segsum += t;
                }
                atomicAdd(&rs[eg], segsum);
            }
        }
    }
    __syncthreads();
    if (threadIdx.x < B_N) {
        float v = rs[threadIdx.x];
        if (v != 0.f) atomicAdd(&g_rowsum[threadIdx.x], v);
    }
}

__global__ void norm_kernel(float* out) {
    int i = blockIdx.x * blockDim.x + threadIdx.x;
    if (i < B_N * N_N) out[i] = out[i] / g_rowsum[i / N_N];
}

// ---------------- launch ----------------
extern "C" void kernel_launch(void* const* d_in, const int* in_sizes, int n_in,
                              void* d_out, int out_size)
{
    const float* na        = (const float*)d_in[0];
    const int*   edges     = (const int*)d_in[1];
    const float* h_uncon   = (const float*)d_in[2];
    const float* h_con     = (const float*)d_in[3];
    const float* rel_table = (const float*)d_in[4];
    const float* qh        = (const float*)d_in[5];
    const float* qr        = (const float*)d_in[6];
    const float* pW        = (const float*)d_in[7];
    const float* pb        = (const float*)d_in[8];
    const float* g1_lW     = (const float*)d_in[9];
    const float* g1_lb     = (const float*)d_in[10];
    const float* g1_rW     = (const float*)d_in[11];
    const float* g1_rb     = (const float*)d_in[12];
    const float* g1_cW     = (const float*)d_in[13];
    const float* g1_cb     = (const float*)d_in[14];
    const float* g2_lW     = (const float*)d_in[15];
    const float* g2_lb     = (const float*)d_in[16];
    const float* g2_rW     = (const float*)d_in[17];
    const float* g2_rb     = (const float*)d_in[18];
    const float* g2_cW     = (const float*)d_in[19];
    const float* g2_cb     = (const float*)d_in[20];
    float* out = (float*)d_out;

    const int PROJ_SMEM = (PR * PSTR + DIN * D_ + 64) * 4;                 // 78656
    const int EDGE_SMEM = (64 * TE + 64 * 64) * 4 + 32 * 128 * 8 + 5 * TE * 4 + TE * 4;  // 84992
    cudaFuncSetAttribute(proj6_kernel, cudaFuncAttributeMaxDynamicSharedMemorySize, PROJ_SMEM);
    cudaFuncSetAttribute(edge4_kernel, cudaFuncAttributeMaxDynamicSharedMemorySize, EDGE_SMEM);

    init_nused_kernel<<<(B_N * N_N + 255) / 256, 256>>>(out, B_N * N_N, edges);

    proj6_kernel<<<(M_N + PR - 1) / PR, 256, PROJ_SMEM>>>(h_con,   pW, pb, M_N, 0, nullptr, nullptr);
    proj6_kernel<<<(N_N + PR - 1) / PR, 256, PROJ_SMEM>>>(h_uncon, pW, pb, N_N, 1, nullptr, nullptr);
    proj6_kernel<<<5, 256, PROJ_SMEM>>>(rel_table, pW, pb, R_N, 5, qh, qr);

    tables_kernel<<<4 * R_N + 4 * B_N, 64>>>(g1_lW, g1_rW, g2_lW, g2_rW,
                                             g1_lb, g1_rb, g2_lb, g2_rb);

    edge4_kernel<<<(E_N + TE - 1) / TE, TE, EDGE_SMEM>>>(edges,
        g1_lW, g1_rW, g1_cW, g1_cb, g2_lW, g2_rW, g2_cW, g2_cb);

    seg_kernel<<<(E_N + 255) / 256, 256>>>(edges, na, out);
    norm_kernel<<<(B_N * N_N + 255) / 256, 256>>>(out);
}

// round 15
// speedup vs baseline: 1.1094x; 1.0321x over previous
#include <cuda_runtime.h>
#include <math.h>

#define E_N 250000
#define B_N 16
#define N_N 50000
#define R_N 500
#define DIN 100
#define D_  64
#define M_N 500000
#define TE  128   // edges per block in edge kernel
#define PR  128   // rows per tile in proj kernel
#define PSTR 103  // Xs row stride (odd -> conflict-free scalar A reads)

#define MB_ ((M_N + PR - 1) / PR)   // 3907
#define NB_ ((N_N + PR - 1) / PR)   // 391

typedef unsigned long long ull;

// ---------------- f32x2 helpers ----------------
__device__ __forceinline__ ull dup2(float x) {
    ull r; asm("mov.b64 %0, {%1, %1};" : "=l"(r) : "f"(x)); return r;
}
__device__ __forceinline__ ull pk2(float x, float y) {
    ull r; asm("mov.b64 %0, {%1, %2};" : "=l"(r) : "f"(x), "f"(y)); return r;
}
__device__ __forceinline__ float2 unp2(ull v) {
    float2 f; asm("mov.b64 {%0, %1}, %2;" : "=f"(f.x), "=f"(f.y) : "l"(v)); return f;
}
__device__ __forceinline__ void fma2(ull& d, ull a, ull b) {
    asm("fma.rn.f32x2 %0, %1, %2, %0;" : "+l"(d) : "l"(a), "l"(b));
}
__device__ __forceinline__ ull add2(ull a, ull b) {
    ull r; asm("add.rn.f32x2 %0, %1, %2;" : "=l"(r) : "l"(a), "l"(b)); return r;
}
__device__ __forceinline__ ull leaky2(ull v) {
    float2 f = unp2(v);
    f.x = fmaxf(f.x, 0.2f * f.x);
    f.y = fmaxf(f.y, 0.2f * f.y);
    return pk2(f.x, f.y);
}
__device__ __forceinline__ float tanh_fast(float x) {
    float e = __expf(2.f * x);
    return __fdividef(e - 1.f, e + 1.f);
}

// ---------------- device scratch ----------------
__device__ float g_P[(size_t)M_N * D_];     // proj(hidden_con)
__device__ float g_PU[(size_t)N_N * D_];    // proj(hidden_uncon)
__device__ float g_relproj[R_N * D_];
__device__ float g_qproj[2 * B_N * D_];     // [qh ; qr]
__device__ float g_relc[4][R_N * D_];       // t: 0=g1l 1=g1r 2=g2l 3=g2r
__device__ float g_qc[4][B_N * D_];         // includes l/r bias
__device__ float g_logits[E_N];
__device__ float g_rowsum[B_N];
__device__ int   g_nused;

// ---------------- fused init + nused ----------------
__global__ void init_nused_kernel(float* out, int total, const int* __restrict__ edges) {
    int i = blockIdx.x * blockDim.x + threadIdx.x;
    if (i < total) out[i] = 0.f;
    if (i < B_N) g_rowsum[i] = 0.f;
    if (i == 0) g_nused = 0;
    __shared__ int s[256];
    int m = 0;
    int stride = gridDim.x * blockDim.x;
    for (int j = i; j < E_N; j += stride)
        m = max(m, __ldg(&edges[j * 8 + 7]));
    s[threadIdx.x] = m;
    __syncthreads();
    for (int o = 128; o > 0; o >>= 1) {
        if (threadIdx.x < o) s[threadIdx.x] = max(s[threadIdx.x], s[threadIdx.x + o]);
        __syncthreads();
    }
    if (threadIdx.x == 0) atomicMax(&g_nused, s[0] + 1);
}

// ---------------- projection (single launch, block-range dispatch):
// blocks [0, MB_)            -> g_P   (guarded by g_nused)
// blocks [MB_, MB_+NB_)      -> g_PU
// blocks [MB_+NB_, +4)       -> g_relproj (4 tiles of 128 rows, 500 used)
// block   MB_+NB_+4          -> g_qproj   (qh rows 0..15, qr rows 16..31)
__global__ void __launch_bounds__(256) projall_kernel(
    const float* __restrict__ h_con, const float* __restrict__ h_uncon,
    const float* __restrict__ rel_table,
    const float* __restrict__ qh, const float* __restrict__ qr,
    const float* __restrict__ pW, const float* __restrict__ pb)
{
    extern __shared__ __align__(16) float psm[];
    float* Xs  = psm;                  // 128*103 = 13184
    float* Ws  = psm + PR * PSTR;      // 100*64  = 6400
    float* pbs = Ws + DIN * D_;        // 64

    int b = blockIdx.x;
    const float* src = nullptr;
    float* dst;
    int rows_eff, row0;
    int mode;   // 0 = big contiguous, 1 = q-combined
    if (b < MB_) {
        src = h_con; dst = g_P;
        rows_eff = min(M_N, g_nused); row0 = b * PR;
        if (row0 >= rows_eff) return;
        mode = 0;
    } else if (b < MB_ + NB_) {
        src = h_uncon; dst = g_PU;
        rows_eff = N_N; row0 = (b - MB_) * PR;
        mode = 0;
    } else if (b < MB_ + NB_ + 4) {
        src = rel_table; dst = g_relproj;
        rows_eff = R_N; row0 = (b - MB_ - NB_) * PR;
        if (row0 >= rows_eff) return;
        mode = 0;
    } else {
        dst = g_qproj; rows_eff = 2 * B_N; row0 = 0;
        mode = 1;
    }

    int tid = threadIdx.x;

    // stage W coalesced (100x64 = 1600 float4)
    #pragma unroll
    for (int i = 0; i < 6; i++)
        ((float4*)Ws)[tid + i * 256] = ((const float4*)pW)[tid + i * 256];
    if (tid < 1600 - 6 * 256)
        ((float4*)Ws)[tid + 6 * 256] = ((const float4*)pW)[tid + 6 * 256];
    if (tid < 64) pbs[tid] = pb[tid];

    // stage A
    if (mode == 0 && row0 + PR <= rows_eff) {
        const float2* s2 = (const float2*)(src + (size_t)row0 * DIN);
        #pragma unroll
        for (int it = 0; it < 25; it++) {
            int i = tid + it * 256;
            int r = i / 50, k2 = i - r * 50;
            float2 v = s2[i];
            Xs[r * PSTR + k2 * 2]     = v.x;
            Xs[r * PSTR + k2 * 2 + 1] = v.y;
        }
    } else if (mode == 1) {
        for (int i = tid; i < 6400; i += 256) {
            int r = i / 50, k2 = i - r * 50;
            float2 v = make_float2(0.f, 0.f);
            if (r < B_N) v = ((const float2*)(qh + (size_t)r * DIN))[k2];
            else if (r < 2 * B_N) v = ((const float2*)(qr + (size_t)(r - B_N) * DIN))[k2];
            Xs[r * PSTR + k2 * 2]     = v.x;
            Xs[r * PSTR + k2 * 2 + 1] = v.y;
        }
    } else {
        for (int i = tid; i < 6400; i += 256) {
            int r = i / 50, k2 = i - r * 50;
            int gr = row0 + r;
            float2 v = (gr < rows_eff)
                     ? ((const float2*)(src + (size_t)gr * DIN))[k2]
                     : make_float2(0.f, 0.f);
            Xs[r * PSTR + k2 * 2]     = v.x;
            Xs[r * PSTR + k2 * 2 + 1] = v.y;
        }
    }
    __syncthreads();

    const int er = tid & 31, cr = tid >> 5;
    const float* xrow = Xs + er * PSTR;

    ull acc[4][4];
    #pragma unroll
    for (int i = 0; i < 4; i++)
        #pragma unroll
        for (int j = 0; j < 4; j++) acc[i][j] = 0ull;

    #pragma unroll 4
    for (int k = 0; k < DIN; k++) {
        float a[4];
        #pragma unroll
        for (int i = 0; i < 4; i++) a[i] = xrow[i * (32 * PSTR) + k];
        ulonglong2 b01 = *(const ulonglong2*)&Ws[k * 64 + cr * 8];
        ulonglong2 b23 = *(const ulonglong2*)&Ws[k * 64 + cr * 8 + 4];
        #pragma unroll
        for (int i = 0; i < 4; i++) {
            ull ad = dup2(a[i]);
            fma2(acc[i][0], ad, b01.x);
            fma2(acc[i][1], ad, b01.y);
            fma2(acc[i][2], ad, b23.x);
            fma2(acc[i][3], ad, b23.y);
        }
    }

    // epilogue: bias + tanh, direct STG (two float4 per row)
    float4 pb0 = *(const float4*)&pbs[cr * 8];
    float4 pb1 = *(const float4*)&pbs[cr * 8 + 4];
    #pragma unroll
    for (int i = 0; i < 4; i++) {
        int gr = row0 + er + 32 * i;
        if (gr < rows_eff) {
            float2 f0 = unp2(acc[i][0]), f1 = unp2(acc[i][1]);
            float2 f2 = unp2(acc[i][2]), f3 = unp2(acc[i][3]);
            float4 o0, o1;
            o0.x = tanh_fast(f0.x + pb0.x);
            o0.y = tanh_fast(f0.y + pb0.y);
            o0.z = tanh_fast(f1.x + pb0.z);
            o0.w = tanh_fast(f1.y + pb0.w);
            o1.x = tanh_fast(f2.x + pb1.x);
            o1.y = tanh_fast(f2.y + pb1.y);
            o1.z = tanh_fast(f3.x + pb1.z);
            o1.w = tanh_fast(f3.y + pb1.w);
            float4* dp = (float4*)(dst + (size_t)gr * D_ + cr * 8);
            dp[0] = o0;
            dp[1] = o1;
        }
    }
}

// ---------------- fused rel + q contribution tables ----------------
__global__ void tables_kernel(
    const float* __restrict__ g1_lW, const float* __restrict__ g1_rW,
    const float* __restrict__ g2_lW, const float* __restrict__ g2_rW,
    const float* __restrict__ g1_lb, const float* __restrict__ g1_rb,
    const float* __restrict__ g2_lb, const float* __restrict__ g2_rb)
{
    int b = blockIdx.x;
    int c = threadIdx.x;
    if (b < 4 * R_N) {
        int t = b / R_N, r = b % R_N;
        const float* W = (t == 0) ? g1_lW : (t == 1) ? g1_rW : (t == 2) ? g2_lW : g2_rW;
        __shared__ float x[64];
        x[c] = g_relproj[r * 64 + c];
        __syncthreads();
        float s = 0.f;
        #pragma unroll
        for (int k = 0; k < 64; k++) s += x[k] * W[(64 + k) * 64 + c];
        g_relc[t][r * 64 + c] = s;
    } else {
        int bb = b - 4 * R_N;
        int t = bb / B_N, q = bb % B_N;
        const float* W  = (t == 0) ? g1_lW : (t == 1) ? g1_rW : (t == 2) ? g2_lW : g2_rW;
        const float* bi = (t == 0) ? g1_lb : (t == 1) ? g1_rb : (t == 2) ? g2_lb : g2_rb;
        __shared__ float xh[64], xr[64];
        xh[c] = g_qproj[q * 64 + c];
        xr[c] = g_qproj[B_N * 64 + q * 64 + c];
        __syncthreads();
        float s = bi[c];
        #pragma unroll
        for (int k = 0; k < 64; k++) {
            s += xh[k] * W[(128 + k) * 64 + c];
            s += xr[k] * W[(192 + k) * 64 + c];
        }
        g_qc[t][q * 64 + c] = s;
    }
}

// ---------------- edge kernel v4b (proven): 128-edge tile, 8x8 frags,
// f32x2, 32-slot smem hold
__global__ void __launch_bounds__(128) edge4_kernel(
    const int* __restrict__ edges,
    const float* __restrict__ g1_lW, const float* __restrict__ g1_rW,
    const float* __restrict__ g1_cW, const float* __restrict__ g1_cb,
    const float* __restrict__ g2_lW, const float* __restrict__ g2_rW,
    const float* __restrict__ g2_cW, const float* __restrict__ g2_cb)
{
    extern __shared__ __align__(16) char smraw[];
    float* Xs      = (float*)smraw;            // [64][128] = 32KB
    float* Ws      = Xs + 64 * TE;             // [64][64]  = 16KB
    ull*   Cs      = (ull*)(Ws + 64 * 64);     // 32 slots x 128 thr = 32KB
    int*   em_eg   = (int*)(Cs + 32 * 128);
    int*   em_rel  = em_eg + TE;
    int*   em_r2   = em_rel + TE;
    int*   em_r6   = em_r2 + TE;
    int*   em_r7   = em_r6 + TE;
    float* logit_s = (float*)(em_r7 + TE);     // [128]

    int tid = threadIdx.x;
    int b0 = blockIdx.x * TE;

    {
        int e = b0 + tid; if (e > E_N - 1) e = E_N - 1;
        int4 m0 = ((const int4*)edges)[(size_t)e * 2];
        int4 m1 = ((const int4*)edges)[(size_t)e * 2 + 1];
        em_eg[tid]  = m0.x;
        em_r2[tid]  = m0.z;   // vj (for h_uncon)
        em_rel[tid] = m0.w;   // rel
        em_r6[tid]  = m1.z;   // idx for h_vi
        em_r7[tid]  = m1.w;   // idx for h_vj
    }
    logit_s[tid] = 0.f;
    __syncthreads();

    const int er = tid & 15, cr = tid >> 4;

    int rel_r[8], eg_r[8];
    #pragma unroll
    for (int i = 0; i < 8; i++) { rel_r[i] = em_rel[er * 8 + i]; eg_r[i] = em_eg[er * 8 + i]; }

    ull acc[8][4], dot2[8];
    #pragma unroll
    for (int i = 0; i < 8; i++) dot2[i] = 0ull;

    auto loadW = [&](const float* __restrict__ W) {
        const float4* s = (const float4*)W;
        float4* d = (float4*)Ws;
        #pragma unroll
        for (int i = 0; i < 8; i++) d[tid + i * 128] = s[tid + i * 128];
    };
    auto gatherP = [&](const float* __restrict__ tab, const int* ridx) {
        int r = ridx[tid];
        const float4* s = (const float4*)(tab + (size_t)r * 64);
        #pragma unroll
        for (int q = 0; q < 16; q++) {
            float4 v = s[q];
            Xs[(q * 4 + 0) * TE + tid] = v.x;
            Xs[(q * 4 + 1) * TE + tid] = v.y;
            Xs[(q * 4 + 2) * TE + tid] = v.z;
            Xs[(q * 4 + 3) * TE + tid] = v.w;
        }
    };
    auto gemm = [&]() {
        #pragma unroll
        for (int i = 0; i < 8; i++)
            #pragma unroll
            for (int jp = 0; jp < 4; jp++) acc[i][jp] = 0ull;
        #pragma unroll 4
        for (int k = 0; k < 64; k++) {
            float a[8];
            *(float4*)&a[0] = *(const float4*)&Xs[k * TE + er * 8];
            *(float4*)&a[4] = *(const float4*)&Xs[k * TE + er * 8 + 4];
            ulonglong2 b01 = *(const ulonglong2*)&Ws[k * 64 + cr * 8];
            ulonglong2 b23 = *(const ulonglong2*)&Ws[k * 64 + cr * 8 + 4];
            #pragma unroll
            for (int i = 0; i < 8; i++) {
                ull ad = dup2(a[i]);
                fma2(acc[i][0], ad, b01.x);
                fma2(acc[i][1], ad, b01.y);
                fma2(acc[i][2], ad, b23.x);
                fma2(acc[i][3], ad, b23.y);
            }
        }
    };
    auto epi = [&](const float* __restrict__ relcT, const float* __restrict__ qcT) {
        #pragma unroll
        for (int i = 0; i < 8; i++) {
            const float4* rp = (const float4*)(relcT + rel_r[i] * 64 + cr * 8);
            const float4* qp = (const float4*)(qcT + eg_r[i] * 64 + cr * 8);
            float4 r0 = rp[0], r1 = rp[1], q0 = qp[0], q1 = qp[1];
            acc[i][0] = leaky2(add2(acc[i][0], pk2(r0.x + q0.x, r0.y + q0.y)));
            acc[i][1] = leaky2(add2(acc[i][1], pk2(r0.z + q0.z, r0.w + q0.w)));
            acc[i][2] = leaky2(add2(acc[i][2], pk2(r1.x + q1.x, r1.y + q1.y)));
            acc[i][3] = leaky2(add2(acc[i][3], pk2(r1.z + q1.z, r1.w + q1.w)));
        }
    };
    auto writeR = [&]() {
        float Rf[8][8];
        #pragma unroll
        for (int i = 0; i < 8; i++) {
            float2 f0 = unp2(acc[i][0]), f1 = unp2(acc[i][1]);
            float2 f2 = unp2(acc[i][2]), f3 = unp2(acc[i][3]);
            Rf[i][0] = f0.x; Rf[i][1] = f0.y; Rf[i][2] = f1.x; Rf[i][3] = f1.y;
            Rf[i][4] = f2.x; Rf[i][5] = f2.y; Rf[i][6] = f3.x; Rf[i][7] = f3.y;
        }
        #pragma unroll
        for (int j = 0; j < 8; j++) {
            int c = cr * 8 + j;
            float4 v0 = make_float4(Rf[0][j], Rf[1][j], Rf[2][j], Rf[3][j]);
            float4 v1 = make_float4(Rf[4][j], Rf[5][j], Rf[6][j], Rf[7][j]);
            *(float4*)&Xs[c * TE + er * 8]     = v0;
            *(float4*)&Xs[c * TE + er * 8 + 4] = v1;
        }
    };
    auto loadCbp = [&](const float* __restrict__ cb, ull cbp[4]) {
        float4 c0 = *(const float4*)(cb + cr * 8);
        float4 c1 = *(const float4*)(cb + cr * 8 + 4);
        cbp[0] = pk2(c0.x, c0.y); cbp[1] = pk2(c0.z, c0.w);
        cbp[2] = pk2(c1.x, c1.y); cbp[3] = pk2(c1.z, c1.w);
    };

    // step 1: R1 = leaky(P[r7] @ g1_rW_x + relc1 + qc1)
    gatherP(g_P, em_r7); loadW(g1_rW);
    __syncthreads();
    gemm(); epi(g_relc[1], g_qc[1]);
    __syncthreads();
    // step 2: C1 = R1 @ g1_cW + cb1 -> Cs (thread-private smem hold)
    writeR(); loadW(g1_cW);
    __syncthreads();
    gemm();
    {
        ull cbp[4]; loadCbp(g1_cb, cbp);
        #pragma unroll
        for (int i = 0; i < 8; i++)
            #pragma unroll
            for (int jp = 0; jp < 4; jp++)
                Cs[(i * 4 + jp) * 128 + tid] = add2(acc[i][jp], cbp[jp]);
    }
    __syncthreads();
    // step 3: L1 = leaky(P[r6] @ g1_lW_x + ...); dot2 += L1 . Cs
    gatherP(g_P, em_r6); loadW(g1_lW);
    __syncthreads();
    gemm(); epi(g_relc[0], g_qc[0]);
    #pragma unroll
    for (int i = 0; i < 8; i++)
        #pragma unroll
        for (int jp = 0; jp < 4; jp++)
            fma2(dot2[i], acc[i][jp], Cs[(i * 4 + jp) * 128 + tid]);
    __syncthreads();
    // step 4: L2 (same X) -> Cs
    loadW(g2_lW);
    __syncthreads();
    gemm(); epi(g_relc[2], g_qc[2]);
    #pragma unroll
    for (int i = 0; i < 8; i++)
        #pragma unroll
        for (int jp = 0; jp < 4; jp++)
            Cs[(i * 4 + jp) * 128 + tid] = acc[i][jp];
    __syncthreads();
    // step 5: R2 = leaky(PU[vj] @ g2_rW_x + ...)
    gatherP(g_PU, em_r2); loadW(g2_rW);
    __syncthreads();
    gemm(); epi(g_relc[3], g_qc[3]);
    __syncthreads();
    // step 6: C2 = R2 @ g2_cW + cb2; dot2 += Cs(L2) . (C2+cb2)
    writeR(); loadW(g2_cW);
    __syncthreads();
    gemm();
    {
        ull cbp[4]; loadCbp(g2_cb, cbp);
        #pragma unroll
        for (int i = 0; i < 8; i++)
            #pragma unroll
            for (int jp = 0; jp < 4; jp++)
                fma2(dot2[i], Cs[(i * 4 + jp) * 128 + tid], add2(acc[i][jp], cbp[jp]));
    }

    // reduce over cr, write logits
    #pragma unroll
    for (int i = 0; i < 8; i++) {
        float2 f = unp2(dot2[i]);
        float p = f.x + f.y;
        p += __shfl_xor_sync(0xffffffffu, p, 16);
        if ((cr & 1) == 0) atomicAdd(&logit_s[er * 8 + i], p);
    }
    __syncthreads();
    if (b0 + tid < E_N) g_logits[b0 + tid] = logit_s[tid];
}

// ---------------- segmented softmax + scatter (length-1 fast path) ----------------
__global__ void seg_kernel(const int* __restrict__ edges, const float* __restrict__ na,
                           float* __restrict__ out)
{
    __shared__ float rs[B_N];
    if (threadIdx.x < B_N) rs[threadIdx.x] = 0.f;
    __syncthreads();

    int i = blockIdx.x * blockDim.x + threadIdx.x;
    if (i < E_N) {
        int ivi = __ldg(&edges[i * 8 + 4]);
        bool head = (i == 0) || (__ldg(&edges[(i - 1) * 8 + 4]) != ivi);
        if (head) {
            int j = i + 1;
            while (j < E_N && __ldg(&edges[j * 8 + 4]) == ivi) j++;
            int eg = edges[i * 8 + 0], vi = edges[i * 8 + 1];
            float base = __ldg(&na[eg * N_N + vi]);
            if (j == i + 1) {
                atomicAdd(&out[eg * N_N + edges[i * 8 + 2]], base);
                atomicAdd(&rs[eg], base);
            } else {
                float m = -1e30f;
                for (int q = i; q < j; q++) m = fmaxf(m, g_logits[q]);
                float den = 0.f;
                for (int q = i; q < j; q++) den += __expf(g_logits[q] - m);
                float inv = base / den;
                float segsum = 0.f;
                for (int q = i; q < j; q++) {
                    int vj = edges[q * 8 + 2];
                    float t = __expf(g_logits[q] - m) * inv;
                    atomicAdd(&out[eg * N_N + vj], t);
                    segsum += t;
                }
                atomicAdd(&rs[eg], segsum);
            }
        }
    }
    __syncthreads();
    if (threadIdx.x < B_N) {
        float v = rs[threadIdx.x];
        if (v != 0.f) atomicAdd(&g_rowsum[threadIdx.x], v);
    }
}

__global__ void norm_kernel(float* out) {
    int i = blockIdx.x * blockDim.x + threadIdx.x;
    if (i < B_N * N_N) out[i] = out[i] / g_rowsum[i / N_N];
}

// ---------------- launch ----------------
extern "C" void kernel_launch(void* const* d_in, const int* in_sizes, int n_in,
                              void* d_out, int out_size)
{
    const float* na        = (const float*)d_in[0];
    const int*   edges     = (const int*)d_in[1];
    const float* h_uncon   = (const float*)d_in[2];
    const float* h_con     = (const float*)d_in[3];
    const float* rel_table = (const float*)d_in[4];
    const float* qh        = (const float*)d_in[5];
    const float* qr        = (const float*)d_in[6];
    const float* pW        = (const float*)d_in[7];
    const float* pb        = (const float*)d_in[8];
    const float* g1_lW     = (const float*)d_in[9];
    const float* g1_lb     = (const float*)d_in[10];
    const float* g1_rW     = (const float*)d_in[11];
    const float* g1_rb     = (const float*)d_in[12];
    const float* g1_cW     = (const float*)d_in[13];
    const float* g1_cb     = (const float*)d_in[14];
    const float* g2_lW     = (const float*)d_in[15];
    const float* g2_lb     = (const float*)d_in[16];
    const float* g2_rW     = (const float*)d_in[17];
    const float* g2_rb     = (const float*)d_in[18];
    const float* g2_cW     = (const float*)d_in[19];
    const float* g2_cb     = (const float*)d_in[20];
    float* out = (float*)d_out;

    const int PROJ_SMEM = (PR * PSTR + DIN * D_ + 64) * 4;                 // 78656
    const int EDGE_SMEM = (64 * TE + 64 * 64) * 4 + 32 * 128 * 8 + 5 * TE * 4 + TE * 4;  // 84992
    cudaFuncSetAttribute(projall_kernel, cudaFuncAttributeMaxDynamicSharedMemorySize, PROJ_SMEM);
    cudaFuncSetAttribute(edge4_kernel, cudaFuncAttributeMaxDynamicSharedMemorySize, EDGE_SMEM);

    init_nused_kernel<<<(B_N * N_N + 255) / 256, 256>>>(out, B_N * N_N, edges);

    projall_kernel<<<MB_ + NB_ + 5, 256, PROJ_SMEM>>>(
        h_con, h_uncon, rel_table, qh, qr, pW, pb);

    tables_kernel<<<4 * R_N + 4 * B_N, 64>>>(g1_lW, g1_rW, g2_lW, g2_rW,
                                             g1_lb, g1_rb, g2_lb, g2_rb);

    edge4_kernel<<<(E_N + TE - 1) / TE, TE, EDGE_SMEM>>>(edges,
        g1_lW, g1_rW, g1_cW, g1_cb, g2_lW, g2_rW, g2_cW, g2_cb);

    seg_kernel<<<(E_N + 255) / 256, 256>>>(edges, na, out);
    norm_kernel<<<(B_N * N_N + 255) / 256, 256>>>(out);
}

// round 16
// speedup vs baseline: 1.1281x; 1.0169x over previous
#include <cuda_runtime.h>
#include <math.h>

#define E_N 250000
#define B_N 16
#define N_N 50000
#define R_N 500
#define DIN 100
#define D_  64
#define M_N 500000
#define TE  128   // edges per block in edge kernel
#define PR  128   // rows per tile in proj kernel
#define PSTR 103  // Xs row stride (odd -> conflict-free scalar A reads)

#define MB_ ((M_N + PR - 1) / PR)   // 3907
#define NB_ ((N_N + PR - 1) / PR)   // 391

typedef unsigned long long ull;

// ---------------- f32x2 helpers ----------------
__device__ __forceinline__ ull dup2(float x) {
    ull r; asm("mov.b64 %0, {%1, %1};" : "=l"(r) : "f"(x)); return r;
}
__device__ __forceinline__ ull pk2(float x, float y) {
    ull r; asm("mov.b64 %0, {%1, %2};" : "=l"(r) : "f"(x), "f"(y)); return r;
}
__device__ __forceinline__ float2 unp2(ull v) {
    float2 f; asm("mov.b64 {%0, %1}, %2;" : "=f"(f.x), "=f"(f.y) : "l"(v)); return f;
}
__device__ __forceinline__ void fma2(ull& d, ull a, ull b) {
    asm("fma.rn.f32x2 %0, %1, %2, %0;" : "+l"(d) : "l"(a), "l"(b));
}
__device__ __forceinline__ ull add2(ull a, ull b) {
    ull r; asm("add.rn.f32x2 %0, %1, %2;" : "=l"(r) : "l"(a), "l"(b)); return r;
}
__device__ __forceinline__ ull leaky2(ull v) {
    float2 f = unp2(v);
    f.x = fmaxf(f.x, 0.2f * f.x);
    f.y = fmaxf(f.y, 0.2f * f.y);
    return pk2(f.x, f.y);
}
__device__ __forceinline__ float tanh_fast(float x) {
    float e = __expf(2.f * x);
    return __fdividef(e - 1.f, e + 1.f);
}

// ---------------- device scratch ----------------
__device__ float g_P[(size_t)M_N * D_];     // proj(hidden_con)
__device__ float g_PU[(size_t)N_N * D_];    // proj(hidden_uncon)
__device__ float g_relproj[R_N * D_];
__device__ float g_qproj[2 * B_N * D_];     // [qh ; qr]
__device__ float g_relc[4][R_N * D_];       // t: 0=g1l 1=g1r 2=g2l 3=g2r
__device__ float g_qc[4][B_N * D_];         // includes l/r bias
__device__ float g_logits[E_N];
__device__ float g_rowsum[B_N];
__device__ int   g_nused;

// ---------------- fused init + nused ----------------
__global__ void init_nused_kernel(float* out, int total, const int* __restrict__ edges) {
    int i = blockIdx.x * blockDim.x + threadIdx.x;
    if (i < total) out[i] = 0.f;
    if (i < B_N) g_rowsum[i] = 0.f;
    if (i == 0) g_nused = 0;
    __shared__ int s[256];
    int m = 0;
    int stride = gridDim.x * blockDim.x;
    for (int j = i; j < E_N; j += stride)
        m = max(m, __ldg(&edges[j * 8 + 7]));
    s[threadIdx.x] = m;
    __syncthreads();
    for (int o = 128; o > 0; o >>= 1) {
        if (threadIdx.x < o) s[threadIdx.x] = max(s[threadIdx.x], s[threadIdx.x + o]);
        __syncthreads();
    }
    if (threadIdx.x == 0) atomicMax(&g_nused, s[0] + 1);
}

// ---------------- projection (single launch, block-range dispatch) ----------------
__global__ void __launch_bounds__(256) projall_kernel(
    const float* __restrict__ h_con, const float* __restrict__ h_uncon,
    const float* __restrict__ rel_table,
    const float* __restrict__ qh, const float* __restrict__ qr,
    const float* __restrict__ pW, const float* __restrict__ pb)
{
    extern __shared__ __align__(16) float psm[];
    float* Xs  = psm;                  // 128*103 = 13184
    float* Ws  = psm + PR * PSTR;      // 100*64  = 6400
    float* pbs = Ws + DIN * D_;        // 64

    int b = blockIdx.x;
    const float* src = nullptr;
    float* dst;
    int rows_eff, row0;
    int mode;   // 0 = big contiguous, 1 = q-combined
    if (b < MB_) {
        src = h_con; dst = g_P;
        rows_eff = min(M_N, g_nused); row0 = b * PR;
        if (row0 >= rows_eff) return;
        mode = 0;
    } else if (b < MB_ + NB_) {
        src = h_uncon; dst = g_PU;
        rows_eff = N_N; row0 = (b - MB_) * PR;
        mode = 0;
    } else if (b < MB_ + NB_ + 4) {
        src = rel_table; dst = g_relproj;
        rows_eff = R_N; row0 = (b - MB_ - NB_) * PR;
        if (row0 >= rows_eff) return;
        mode = 0;
    } else {
        dst = g_qproj; rows_eff = 2 * B_N; row0 = 0;
        mode = 1;
    }

    int tid = threadIdx.x;

    // stage W coalesced (100x64 = 1600 float4)
    #pragma unroll
    for (int i = 0; i < 6; i++)
        ((float4*)Ws)[tid + i * 256] = ((const float4*)pW)[tid + i * 256];
    if (tid < 1600 - 6 * 256)
        ((float4*)Ws)[tid + 6 * 256] = ((const float4*)pW)[tid + 6 * 256];
    if (tid < 64) pbs[tid] = pb[tid];

    // stage A
    if (mode == 0 && row0 + PR <= rows_eff) {
        const float2* s2 = (const float2*)(src + (size_t)row0 * DIN);
        #pragma unroll
        for (int it = 0; it < 25; it++) {
            int i = tid + it * 256;
            int r = i / 50, k2 = i - r * 50;
            float2 v = s2[i];
            Xs[r * PSTR + k2 * 2]     = v.x;
            Xs[r * PSTR + k2 * 2 + 1] = v.y;
        }
    } else if (mode == 1) {
        for (int i = tid; i < 6400; i += 256) {
            int r = i / 50, k2 = i - r * 50;
            float2 v = make_float2(0.f, 0.f);
            if (r < B_N) v = ((const float2*)(qh + (size_t)r * DIN))[k2];
            else if (r < 2 * B_N) v = ((const float2*)(qr + (size_t)(r - B_N) * DIN))[k2];
            Xs[r * PSTR + k2 * 2]     = v.x;
            Xs[r * PSTR + k2 * 2 + 1] = v.y;
        }
    } else {
        for (int i = tid; i < 6400; i += 256) {
            int r = i / 50, k2 = i - r * 50;
            int gr = row0 + r;
            float2 v = (gr < rows_eff)
                     ? ((const float2*)(src + (size_t)gr * DIN))[k2]
                     : make_float2(0.f, 0.f);
            Xs[r * PSTR + k2 * 2]     = v.x;
            Xs[r * PSTR + k2 * 2 + 1] = v.y;
        }
    }
    __syncthreads();

    const int er = tid & 31, cr = tid >> 5;
    const float* xrow = Xs + er * PSTR;

    ull acc[4][4];
    #pragma unroll
    for (int i = 0; i < 4; i++)
        #pragma unroll
        for (int j = 0; j < 4; j++) acc[i][j] = 0ull;

    #pragma unroll 4
    for (int k = 0; k < DIN; k++) {
        float a[4];
        #pragma unroll
        for (int i = 0; i < 4; i++) a[i] = xrow[i * (32 * PSTR) + k];
        ulonglong2 b01 = *(const ulonglong2*)&Ws[k * 64 + cr * 8];
        ulonglong2 b23 = *(const ulonglong2*)&Ws[k * 64 + cr * 8 + 4];
        #pragma unroll
        for (int i = 0; i < 4; i++) {
            ull ad = dup2(a[i]);
            fma2(acc[i][0], ad, b01.x);
            fma2(acc[i][1], ad, b01.y);
            fma2(acc[i][2], ad, b23.x);
            fma2(acc[i][3], ad, b23.y);
        }
    }

    // epilogue: bias + tanh, direct STG (two float4 per row)
    float4 pb0 = *(const float4*)&pbs[cr * 8];
    float4 pb1 = *(const float4*)&pbs[cr * 8 + 4];
    #pragma unroll
    for (int i = 0; i < 4; i++) {
        int gr = row0 + er + 32 * i;
        if (gr < rows_eff) {
            float2 f0 = unp2(acc[i][0]), f1 = unp2(acc[i][1]);
            float2 f2 = unp2(acc[i][2]), f3 = unp2(acc[i][3]);
            float4 o0, o1;
            o0.x = tanh_fast(f0.x + pb0.x);
            o0.y = tanh_fast(f0.y + pb0.y);
            o0.z = tanh_fast(f1.x + pb0.z);
            o0.w = tanh_fast(f1.y + pb0.w);
            o1.x = tanh_fast(f2.x + pb1.x);
            o1.y = tanh_fast(f2.y + pb1.y);
            o1.z = tanh_fast(f3.x + pb1.z);
            o1.w = tanh_fast(f3.y + pb1.w);
            float4* dp = (float4*)(dst + (size_t)gr * D_ + cr * 8);
            dp[0] = o0;
            dp[1] = o1;
        }
    }
}

// ---------------- fused rel + q contribution tables ----------------
__global__ void tables_kernel(
    const float* __restrict__ g1_lW, const float* __restrict__ g1_rW,
    const float* __restrict__ g2_lW, const float* __restrict__ g2_rW,
    const float* __restrict__ g1_lb, const float* __restrict__ g1_rb,
    const float* __restrict__ g2_lb, const float* __restrict__ g2_rb)
{
    int b = blockIdx.x;
    int c = threadIdx.x;
    if (b < 4 * R_N) {
        int t = b / R_N, r = b % R_N;
        const float* W = (t == 0) ? g1_lW : (t == 1) ? g1_rW : (t == 2) ? g2_lW : g2_rW;
        __shared__ float x[64];
        x[c] = g_relproj[r * 64 + c];
        __syncthreads();
        float s = 0.f;
        #pragma unroll
        for (int k = 0; k < 64; k++) s += x[k] * W[(64 + k) * 64 + c];
        g_relc[t][r * 64 + c] = s;
    } else {
        int bb = b - 4 * R_N;
        int t = bb / B_N, q = bb % B_N;
        const float* W  = (t == 0) ? g1_lW : (t == 1) ? g1_rW : (t == 2) ? g2_lW : g2_rW;
        const float* bi = (t == 0) ? g1_lb : (t == 1) ? g1_rb : (t == 2) ? g2_lb : g2_rb;
        __shared__ float xh[64], xr[64];
        xh[c] = g_qproj[q * 64 + c];
        xr[c] = g_qproj[B_N * 64 + q * 64 + c];
        __syncthreads();
        float s = bi[c];
        #pragma unroll
        for (int k = 0; k < 64; k++) {
            s += xh[k] * W[(128 + k) * 64 + c];
            s += xr[k] * W[(192 + k) * 64 + c];
        }
        g_qc[t][q * 64 + c] = s;
    }
}

// ---------------- edge kernel v5: 128-edge tile, 256 THREADS, 4x8 frags,
// f32x2, 16-slot smem hold -> 16 warps/SM at same 85KB smem
__global__ void __launch_bounds__(256) edge5_kernel(
    const int* __restrict__ edges,
    const float* __restrict__ g1_lW, const float* __restrict__ g1_rW,
    const float* __restrict__ g1_cW, const float* __restrict__ g1_cb,
    const float* __restrict__ g2_lW, const float* __restrict__ g2_rW,
    const float* __restrict__ g2_cW, const float* __restrict__ g2_cb)
{
    extern __shared__ __align__(16) char smraw[];
    float* Xs      = (float*)smraw;            // [64][128] = 32KB
    float* Ws      = Xs + 64 * TE;             // [64][64]  = 16KB
    ull*   Cs      = (ull*)(Ws + 64 * 64);     // 16 slots x 256 thr = 32KB
    int*   em_eg   = (int*)(Cs + 16 * 256);
    int*   em_rel  = em_eg + TE;
    int*   em_r2   = em_rel + TE;
    int*   em_r6   = em_r2 + TE;
    int*   em_r7   = em_r6 + TE;
    float* logit_s = (float*)(em_r7 + TE);     // [128]

    int tid = threadIdx.x;
    int b0 = blockIdx.x * TE;

    if (tid < TE) {
        int e = b0 + tid; if (e > E_N - 1) e = E_N - 1;
        int4 m0 = ((const int4*)edges)[(size_t)e * 2];
        int4 m1 = ((const int4*)edges)[(size_t)e * 2 + 1];
        em_eg[tid]  = m0.x;
        em_r2[tid]  = m0.z;   // vj (for h_uncon)
        em_rel[tid] = m0.w;   // rel
        em_r6[tid]  = m1.z;   // idx for h_vi
        em_r7[tid]  = m1.w;   // idx for h_vj
        logit_s[tid] = 0.f;
    }
    __syncthreads();

    const int er = tid & 31, cr = tid >> 5;   // 32 edge-groups x 8 col-groups

    int rel_r[4], eg_r[4];
    #pragma unroll
    for (int i = 0; i < 4; i++) { rel_r[i] = em_rel[er * 4 + i]; eg_r[i] = em_eg[er * 4 + i]; }

    ull acc[4][4], dot2[4];
    #pragma unroll
    for (int i = 0; i < 4; i++) dot2[i] = 0ull;

    auto loadW = [&](const float* __restrict__ W) {
        const float4* s = (const float4*)W;
        float4* d = (float4*)Ws;
        #pragma unroll
        for (int i = 0; i < 4; i++) d[tid + i * 256] = s[tid + i * 256];
    };
    auto gatherP = [&](const float* __restrict__ tab, const int* ridx) {
        int e = tid >> 1, h = tid & 1;
        int r = ridx[e];
        const float4* s = (const float4*)(tab + (size_t)r * 64) + h * 8;
        #pragma unroll
        for (int q = 0; q < 8; q++) {
            float4 v = s[q];
            int k = h * 32 + q * 4;
            Xs[(k + 0) * TE + e] = v.x;
            Xs[(k + 1) * TE + e] = v.y;
            Xs[(k + 2) * TE + e] = v.z;
            Xs[(k + 3) * TE + e] = v.w;
        }
    };
    auto gemm = [&]() {
        #pragma unroll
        for (int i = 0; i < 4; i++)
            #pragma unroll
            for (int jp = 0; jp < 4; jp++) acc[i][jp] = 0ull;
        #pragma unroll 4
        for (int k = 0; k < 64; k++) {
            float a[4];
            *(float4*)a = *(const float4*)&Xs[k * TE + er * 4];
            ulonglong2 b01 = *(const ulonglong2*)&Ws[k * 64 + cr * 8];
            ulonglong2 b23 = *(const ulonglong2*)&Ws[k * 64 + cr * 8 + 4];
            #pragma unroll
            for (int i = 0; i < 4; i++) {
                ull ad = dup2(a[i]);
                fma2(acc[i][0], ad, b01.x);
                fma2(acc[i][1], ad, b01.y);
                fma2(acc[i][2], ad, b23.x);
                fma2(acc[i][3], ad, b23.y);
            }
        }
    };
    auto epi = [&](const float* __restrict__ relcT, const float* __restrict__ qcT) {
        #pragma unroll
        for (int i = 0; i < 4; i++) {
            const float4* rp = (const float4*)(relcT + rel_r[i] * 64 + cr * 8);
            const float4* qp = (const float4*)(qcT + eg_r[i] * 64 + cr * 8);
            float4 r0 = rp[0], r1 = rp[1], q0 = qp[0], q1 = qp[1];
            acc[i][0] = leaky2(add2(acc[i][0], pk2(r0.x + q0.x, r0.y + q0.y)));
            acc[i][1] = leaky2(add2(acc[i][1], pk2(r0.z + q0.z, r0.w + q0.w)));
            acc[i][2] = leaky2(add2(acc[i][2], pk2(r1.x + q1.x, r1.y + q1.y)));
            acc[i][3] = leaky2(add2(acc[i][3], pk2(r1.z + q1.z, r1.w + q1.w)));
        }
    };
    auto writeR = [&]() {
        float Rf[4][8];
        #pragma unroll
        for (int i = 0; i < 4; i++) {
            float2 f0 = unp2(acc[i][0]), f1 = unp2(acc[i][1]);
            float2 f2 = unp2(acc[i][2]), f3 = unp2(acc[i][3]);
            Rf[i][0] = f0.x; Rf[i][1] = f0.y; Rf[i][2] = f1.x; Rf[i][3] = f1.y;
            Rf[i][4] = f2.x; Rf[i][5] = f2.y; Rf[i][6] = f3.x; Rf[i][7] = f3.y;
        }
        #pragma unroll
        for (int j = 0; j < 8; j++) {
            int c = cr * 8 + j;
            *(float4*)&Xs[c * TE + er * 4] =
                make_float4(Rf[0][j], Rf[1][j], Rf[2][j], Rf[3][j]);
        }
    };
    auto loadCbp = [&](const float* __restrict__ cb, ull cbp[4]) {
        float4 c0 = *(const float4*)(cb + cr * 8);
        float4 c1 = *(const float4*)(cb + cr * 8 + 4);
        cbp[0] = pk2(c0.x, c0.y); cbp[1] = pk2(c0.z, c0.w);
        cbp[2] = pk2(c1.x, c1.y); cbp[3] = pk2(c1.z, c1.w);
    };

    // step 1: R1 = leaky(P[r7] @ g1_rW_x + relc1 + qc1)
    gatherP(g_P, em_r7); loadW(g1_rW);
    __syncthreads();
    gemm(); epi(g_relc[1], g_qc[1]);
    __syncthreads();
    // step 2: C1 = R1 @ g1_cW + cb1 -> Cs (thread-private smem hold)
    writeR(); loadW(g1_cW);
    __syncthreads();
    gemm();
    {
        ull cbp[4]; loadCbp(g1_cb, cbp);
        #pragma unroll
        for (int i = 0; i < 4; i++)
            #pragma unroll
            for (int jp = 0; jp < 4; jp++)
                Cs[(i * 4 + jp) * 256 + tid] = add2(acc[i][jp], cbp[jp]);
    }
    __syncthreads();
    // step 3: L1 = leaky(P[r6] @ g1_lW_x + ...); dot2 += L1 . Cs
    gatherP(g_P, em_r6); loadW(g1_lW);
    __syncthreads();
    gemm(); epi(g_relc[0], g_qc[0]);
    #pragma unroll
    for (int i = 0; i < 4; i++)
        #pragma unroll
        for (int jp = 0; jp < 4; jp++)
            fma2(dot2[i], acc[i][jp], Cs[(i * 4 + jp) * 256 + tid]);
    __syncthreads();
    // step 4: L2 (same X) -> Cs
    loadW(g2_lW);
    __syncthreads();
    gemm(); epi(g_relc[2], g_qc[2]);
    #pragma unroll
    for (int i = 0; i < 4; i++)
        #pragma unroll
        for (int jp = 0; jp < 4; jp++)
            Cs[(i * 4 + jp) * 256 + tid] = acc[i][jp];
    __syncthreads();
    // step 5: R2 = leaky(PU[vj] @ g2_rW_x + ...)
    gatherP(g_PU, em_r2); loadW(g2_rW);
    __syncthreads();
    gemm(); epi(g_relc[3], g_qc[3]);
    __syncthreads();
    // step 6: C2 = R2 @ g2_cW + cb2; dot2 += Cs(L2) . (C2+cb2)
    writeR(); loadW(g2_cW);
    __syncthreads();
    gemm();
    {
        ull cbp[4]; loadCbp(g2_cb, cbp);
        #pragma unroll
        for (int i = 0; i < 4; i++)
            #pragma unroll
            for (int jp = 0; jp < 4; jp++)
                fma2(dot2[i], Cs[(i * 4 + jp) * 256 + tid], add2(acc[i][jp], cbp[jp]));
    }

    // reduce over the 8 cr-warps via smem atomics (spread addresses)
    #pragma unroll
    for (int i = 0; i < 4; i++) {
        float2 f = unp2(dot2[i]);
        atomicAdd(&logit_s[er * 4 + i], f.x + f.y);
    }
    __syncthreads();
    if (tid < TE && b0 + tid < E_N) g_logits[b0 + tid] = logit_s[tid];
}

// ---------------- segmented softmax + scatter (length-1 fast path) ----------------
__global__ void seg_kernel(const int* __restrict__ edges, const float* __restrict__ na,
                           float* __restrict__ out)
{
    __shared__ float rs[B_N];
    if (threadIdx.x < B_N) rs[threadIdx.x] = 0.f;
    __syncthreads();

    int i = blockIdx.x * blockDim.x + threadIdx.x;
    if (i < E_N) {
        int ivi = __ldg(&edges[i * 8 + 4]);
        bool head = (i == 0) || (__ldg(&edges[(i - 1) * 8 + 4]) != ivi);
        if (head) {
            int j = i + 1;
            while (j < E_N && __ldg(&edges[j * 8 + 4]) == ivi) j++;
            int eg = edges[i * 8 + 0], vi = edges[i * 8 + 1];
            float base = __ldg(&na[eg * N_N + vi]);
            if (j == i + 1) {
                atomicAdd(&out[eg * N_N + edges[i * 8 + 2]], base);
                atomicAdd(&rs[eg], base);
            } else {
                float m = -1e30f;
                for (int q = i; q < j; q++) m = fmaxf(m, g_logits[q]);
                float den = 0.f;
                for (int q = i; q < j; q++) den += __expf(g_logits[q] - m);
                float inv = base / den;
                float segsum = 0.f;
                for (int q = i; q < j; q++) {
                    int vj = edges[q * 8 + 2];
                    float t = __expf(g_logits[q] - m) * inv;
                    atomicAdd(&out[eg * N_N + vj], t);
                    segsum += t;
                }
                atomicAdd(&rs[eg], segsum);
            }
        }
    }
    __syncthreads();
    if (threadIdx.x < B_N) {
        float v = rs[threadIdx.x];
        if (v != 0.f) atomicAdd(&g_rowsum[threadIdx.x], v);
    }
}

__global__ void norm_kernel(float* out) {
    int i = blockIdx.x * blockDim.x + threadIdx.x;
    if (i < B_N * N_N) out[i] = out[i] / g_rowsum[i / N_N];
}

// ---------------- launch ----------------
extern "C" void kernel_launch(void* const* d_in, const int* in_sizes, int n_in,
                              void* d_out, int out_size)
{
    const float* na        = (const float*)d_in[0];
    const int*   edges     = (const int*)d_in[1];
    const float* h_uncon   = (const float*)d_in[2];
    const float* h_con     = (const float*)d_in[3];
    const float* rel_table = (const float*)d_in[4];
    const float* qh        = (const float*)d_in[5];
    const float* qr        = (const float*)d_in[6];
    const float* pW        = (const float*)d_in[7];
    const float* pb        = (const float*)d_in[8];
    const float* g1_lW     = (const float*)d_in[9];
    const float* g1_lb     = (const float*)d_in[10];
    const float* g1_rW     = (const float*)d_in[11];
    const float* g1_rb     = (const float*)d_in[12];
    const float* g1_cW     = (const float*)d_in[13];
    const float* g1_cb     = (const float*)d_in[14];
    const float* g2_lW     = (const float*)d_in[15];
    const float* g2_lb     = (const float*)d_in[16];
    const float* g2_rW     = (const float*)d_in[17];
    const float* g2_rb     = (const float*)d_in[18];
    const float* g2_cW     = (const float*)d_in[19];
    const float* g2_cb     = (const float*)d_in[20];
    float* out = (float*)d_out;

    const int PROJ_SMEM = (PR * PSTR + DIN * D_ + 64) * 4;                 // 78656
    const int EDGE_SMEM = (64 * TE + 64 * 64) * 4 + 16 * 256 * 8 + 5 * TE * 4 + TE * 4;  // 84992
    cudaFuncSetAttribute(projall_kernel, cudaFuncAttributeMaxDynamicSharedMemorySize, PROJ_SMEM);
    cudaFuncSetAttribute(edge5_kernel, cudaFuncAttributeMaxDynamicSharedMemorySize, EDGE_SMEM);

    init_nused_kernel<<<(B_N * N_N + 255) / 256, 256>>>(out, B_N * N_N, edges);

    projall_kernel<<<MB_ + NB_ + 5, 256, PROJ_SMEM>>>(
        h_con, h_uncon, rel_table, qh, qr, pW, pb);

    tables_kernel<<<4 * R_N + 4 * B_N, 64>>>(g1_lW, g1_rW, g2_lW, g2_rW,
                                             g1_lb, g1_rb, g2_lb, g2_rb);

    edge5_kernel<<<(E_N + TE - 1) / TE, 256, EDGE_SMEM>>>(edges,
        g1_lW, g1_rW, g1_cW, g1_cb, g2_lW, g2_rW, g2_cW, g2_cb);

    seg_kernel<<<(E_N + 255) / 256, 256>>>(edges, na, out);
    norm_kernel<<<(B_N * N_N + 255) / 256, 256>>>(out);
}